// round 1
// baseline (speedup 1.0000x reference)
#include <cuda_runtime.h>
#include <math.h>

#define B_   32
#define S_   64
#define H_   300
#define D_   300
#define L_   20
#define BS_  2048          // B*S
#define G4_  1200          // 4*H
#define VD_  160           // 8*L
#define EPSV 1e-8f

// ------------------------- scratch (static device globals) -------------------
__device__ float g_s1[BS_*D_];
__device__ float g_s2[BS_*D_];
__device__ float g_xg[4*BS_*G4_];        // gate preactivations, reused ctx->agg
__device__ float g_o[4*BS_*H_];          // ctx outputs: s1f,s1b,s2f,s2b
__device__ float g_on[4*BS_*H_];         // row-normalized copies
__device__ float g_hc[4*3*B_*H_];        // per stream: h slot0, h slot1, c
__device__ float g_pair[2*B_*L_*S_*S_];  // [which][B][L][S][S]
__device__ float g_cos[2*B_*S_*S_];
__device__ float g_rsum[2*B_*S_];        // sum over i (axis=1)
__device__ float g_csum[2*B_*S_];        // sum over j (axis=2)
__device__ float g_mean[4*BS_*H_];       // mean_s1_f, mean_s1_b, mean_s2_f, mean_s2_b
__device__ float g_maxv[4*BS_*H_];       // max_s1_f,  max_s1_b,  max_s2_f,  max_s2_b
__device__ float g_v[2*BS_*VD_];         // v1, v2
__device__ float g_x1[B_*600];

// ------------------------------- kernels -------------------------------------

__global__ void zero_kernel(float* p, int n) {
    int i = blockIdx.x * blockDim.x + threadIdx.x;
    if (i < n) p[i] = 0.f;
}

__global__ void gather_emb_kernel(const float* __restrict__ emb,
                                  const int* __restrict__ ia, const int* __restrict__ ib,
                                  float* __restrict__ s1, float* __restrict__ s2) {
    int row = blockIdx.x;
    int a = ia[row], b = ib[row];
    for (int k = threadIdx.x; k < D_; k += blockDim.x) {
        s1[(size_t)row * D_ + k] = emb[(size_t)a * D_ + k];
        s2[(size_t)row * D_ + k] = emb[(size_t)b * D_ + k];
    }
}

// C[M,N] = A[M,K] @ W[N,K]^T + bias[N]
__global__ void gemm_bias_kernel(const float* __restrict__ A, const float* __restrict__ W,
                                 const float* __restrict__ bias, float* __restrict__ C,
                                 int M, int N, int K) {
    __shared__ float As[8][68];
    __shared__ float Bs[8][68];
    int tid = threadIdx.x;
    int ti = tid >> 4, tj = tid & 15;
    int m0 = blockIdx.y * 64, n0 = blockIdx.x * 64;
    float acc[4][4] = {};
    for (int k0 = 0; k0 < K; k0 += 8) {
        #pragma unroll
        for (int r = 0; r < 2; r++) {
            int idx = tid + r * 256;
            int row = idx >> 3, col = idx & 7;
            int kk = k0 + col;
            int m = m0 + row;
            int n = n0 + row;
            As[col][row] = (kk < K && m < M) ? A[(size_t)m * K + kk] : 0.f;
            Bs[col][row] = (kk < K && n < N) ? W[(size_t)n * K + kk] : 0.f;
        }
        __syncthreads();
        #pragma unroll
        for (int kk = 0; kk < 8; kk++) {
            float4 a4 = *(const float4*)&As[kk][ti * 4];
            float4 b4 = *(const float4*)&Bs[kk][tj * 4];
            float av[4] = {a4.x, a4.y, a4.z, a4.w};
            float bv[4] = {b4.x, b4.y, b4.z, b4.w};
            #pragma unroll
            for (int r = 0; r < 4; r++)
                #pragma unroll
                for (int c = 0; c < 4; c++)
                    acc[r][c] += av[r] * bv[c];
        }
        __syncthreads();
    }
    #pragma unroll
    for (int r = 0; r < 4; r++) {
        int m = m0 + ti * 4 + r;
        if (m >= M) continue;
        #pragma unroll
        for (int c = 0; c < 4; c++) {
            int n = n0 + tj * 4 + c;
            if (n < N) C[(size_t)m * N + n] = acc[r][c] + bias[n];
        }
    }
}

// One timestep for 4 independent LSTM streams: {s1 fwd, s1 bwd, s2 fwd, s2 bwd}.
// grid (25, 4), block 384 = 32 batch x 12 hidden columns.
// h-state double buffered in hc slots 0/1 (read slot s&1, write slot (s+1)&1).
__global__ void lstm_step_kernel(const float* __restrict__ xg,
                                 const float* __restrict__ Whf, const float* __restrict__ Whb,
                                 float* __restrict__ hc, float* __restrict__ ys, int s) {
    __shared__ float h_sm[B_ * H_];
    int st   = blockIdx.y;
    int b    = threadIdx.x & 31;
    int mloc = threadIdx.x >> 5;
    int m    = blockIdx.x * 12 + mloc;
    const float* W = (st & 1) ? Whb : Whf;
    int t = (st & 1) ? (S_ - 1 - s) : s;
    float* base = hc + st * 3 * B_ * H_;
    const float* hr = base + (s & 1) * B_ * H_;
    float* hw  = base + ((s + 1) & 1) * B_ * H_;
    float* cst = base + 2 * B_ * H_;
    for (int idx = threadIdx.x; idx < B_ * H_; idx += blockDim.x)
        h_sm[idx] = hr[idx];
    __syncthreads();

    const float* xr = xg + ((size_t)st * BS_ + (size_t)b * S_ + t) * G4_;
    float ai = xr[m], af = xr[H_ + m], ag = xr[2 * H_ + m], ao = xr[3 * H_ + m];
    const float4* wi = (const float4*)(W + (size_t)m * H_);
    const float4* wf = (const float4*)(W + (size_t)(H_ + m) * H_);
    const float4* wg = (const float4*)(W + (size_t)(2 * H_ + m) * H_);
    const float4* wo = (const float4*)(W + (size_t)(3 * H_ + m) * H_);
    const float4* hv = (const float4*)(h_sm + b * H_);
    #pragma unroll 5
    for (int k = 0; k < H_ / 4; k++) {
        float4 h4 = hv[k];
        float4 a = wi[k]; ai += h4.x * a.x + h4.y * a.y + h4.z * a.z + h4.w * a.w;
        float4 f = wf[k]; af += h4.x * f.x + h4.y * f.y + h4.z * f.z + h4.w * f.w;
        float4 g = wg[k]; ag += h4.x * g.x + h4.y * g.y + h4.z * g.z + h4.w * g.w;
        float4 o = wo[k]; ao += h4.x * o.x + h4.y * o.y + h4.z * o.z + h4.w * o.w;
    }
    float c  = cst[b * H_ + m];
    float ii = 1.f / (1.f + expf(-ai));
    float ff = 1.f / (1.f + expf(-af));
    float gg = tanhf(ag);
    float oo = 1.f / (1.f + expf(-ao));
    float cn = ff * c + ii * gg;
    float hn = oo * tanhf(cn);
    cst[b * H_ + m] = cn;
    hw[b * H_ + m]  = hn;
    if (ys) ys[((size_t)(st * B_ + b) * S_ + t) * H_ + m] = hn;
}

__global__ void normalize_kernel(const float* __restrict__ in, float* __restrict__ out, int nrows) {
    int warp = (blockIdx.x * blockDim.x + threadIdx.x) >> 5;
    int lane = threadIdx.x & 31;
    if (warp >= nrows) return;
    const float* r = in + (size_t)warp * H_;
    float ss = 0.f;
    for (int k = lane; k < H_; k += 32) { float v = r[k]; ss += v * v; }
    #pragma unroll
    for (int o = 16; o; o >>= 1) ss += __shfl_xor_sync(0xffffffffu, ss, o);
    float inv = rsqrtf(ss);
    float* w = out + (size_t)warp * H_;
    for (int k = lane; k < H_; k += 32) w[k] = r[k] * inv;
}

// out[b,s,l] = sum_h W2*v1*v2 / (max(||v1||_W,eps)*max(||v2||_W,eps)), written into
// the concatenated matching vector at column offset `off` (row stride VD_).
__global__ void full_match_kernel(const float* __restrict__ v1, const float* __restrict__ v2,
                                  long v2_bs, long v2_ss, const float* __restrict__ Wm,
                                  float* __restrict__ vout, int off) {
    int b = blockIdx.y, sIdx = blockIdx.x;
    __shared__ float a_sm[H_], c_sm[H_];
    const float* a = v1 + ((size_t)b * S_ + sIdx) * H_;
    const float* c = v2 + (size_t)b * v2_bs + (size_t)sIdx * v2_ss;
    for (int k = threadIdx.x; k < H_; k += blockDim.x) { a_sm[k] = a[k]; c_sm[k] = c[k]; }
    __syncthreads();
    int l = threadIdx.x;
    if (l < L_) {
        const float* w = Wm + l * H_;
        float num = 0.f, na = 0.f, nc = 0.f;
        for (int k = 0; k < H_; k++) {
            float wv = w[k]; float w2 = wv * wv;
            float av = a_sm[k], cv = c_sm[k];
            num += w2 * av * cv; na += w2 * av * av; nc += w2 * cv * cv;
        }
        float d = fmaxf(sqrtf(na), EPSV) * fmaxf(sqrtf(nc), EPSV);
        vout[((size_t)b * S_ + sIdx) * VD_ + off + l] = num / d;
    }
}

// m_pair[b,l,i,j] = sum_h W2[l,h] s1n[b,i,h] s2n[b,j,h]  (inputs pre-normalized)
__global__ void pairwise_kernel(const float* __restrict__ s1n, const float* __restrict__ s2n,
                                const float* __restrict__ Wm, float* __restrict__ outp) {
    int l = blockIdx.x, b = blockIdx.y;
    __shared__ float s1w[60][64], s2c[60][64];
    const float* w = Wm + l * H_;
    int tid = threadIdx.x;
    int ti = tid >> 4, tj = tid & 15;
    float acc[4][4] = {};
    for (int h0 = 0; h0 < H_; h0 += 60) {
        for (int idx = tid; idx < 64 * 60; idx += 256) {
            int i = idx / 60, hh = idx % 60;
            float wv = w[h0 + hh];
            size_t gi = ((size_t)b * S_ + i) * H_ + h0 + hh;
            s1w[hh][i] = s1n[gi] * wv * wv;
            s2c[hh][i] = s2n[gi];
        }
        __syncthreads();
        #pragma unroll 4
        for (int hh = 0; hh < 60; hh++) {
            float4 a4 = *(const float4*)&s1w[hh][ti * 4];
            float4 b4 = *(const float4*)&s2c[hh][tj * 4];
            float av[4] = {a4.x, a4.y, a4.z, a4.w};
            float bv[4] = {b4.x, b4.y, b4.z, b4.w};
            #pragma unroll
            for (int r = 0; r < 4; r++)
                #pragma unroll
                for (int c = 0; c < 4; c++)
                    acc[r][c] += av[r] * bv[c];
        }
        __syncthreads();
    }
    float* o = outp + ((size_t)b * L_ + l) * S_ * S_;
    #pragma unroll
    for (int r = 0; r < 4; r++)
        #pragma unroll
        for (int c = 0; c < 4; c++)
            o[(ti * 4 + r) * S_ + tj * 4 + c] = acc[r][c];
}

// cos[b,i,j] = sum_h an[b,i,h] bn[b,j,h]
__global__ void cosine_kernel(const float* __restrict__ an, const float* __restrict__ bn,
                              float* __restrict__ outp) {
    int b = blockIdx.x;
    __shared__ float s1c[60][64], s2c[60][64];
    int tid = threadIdx.x;
    int ti = tid >> 4, tj = tid & 15;
    float acc[4][4] = {};
    for (int h0 = 0; h0 < H_; h0 += 60) {
        for (int idx = tid; idx < 64 * 60; idx += 256) {
            int i = idx / 60, hh = idx % 60;
            size_t gi = ((size_t)b * S_ + i) * H_ + h0 + hh;
            s1c[hh][i] = an[gi];
            s2c[hh][i] = bn[gi];
        }
        __syncthreads();
        #pragma unroll 4
        for (int hh = 0; hh < 60; hh++) {
            float4 a4 = *(const float4*)&s1c[hh][ti * 4];
            float4 b4 = *(const float4*)&s2c[hh][tj * 4];
            float av[4] = {a4.x, a4.y, a4.z, a4.w};
            float bv[4] = {b4.x, b4.y, b4.z, b4.w};
            #pragma unroll
            for (int r = 0; r < 4; r++)
                #pragma unroll
                for (int c = 0; c < 4; c++)
                    acc[r][c] += av[r] * bv[c];
        }
        __syncthreads();
    }
    float* o = outp + (size_t)b * S_ * S_;
    #pragma unroll
    for (int r = 0; r < 4; r++)
        #pragma unroll
        for (int c = 0; c < 4; c++)
            o[(ti * 4 + r) * S_ + tj * 4 + c] = acc[r][c];
}

__global__ void cos_sums_kernel(const float* __restrict__ cosm,
                                float* __restrict__ rsum, float* __restrict__ csum) {
    int b = blockIdx.x, t = threadIdx.x;
    const float* cb = cosm + (size_t)b * S_ * S_;
    float sj = 0.f, si = 0.f;
    for (int k = 0; k < S_; k++) { sj += cb[t * S_ + k]; si += cb[k * S_ + t]; }
    csum[b * S_ + t] = sj;   // axis=2 sum (over j), indexed by i
    rsum[b * S_ + t] = si;   // axis=1 sum (over i), indexed by j
}

__global__ void attn_mean_i_kernel(const float* __restrict__ cosm, const float* __restrict__ src,
                                   const float* __restrict__ dsum, float* __restrict__ outp) {
    int b = blockIdx.y, j = blockIdx.x, h = threadIdx.x;
    if (h >= H_) return;
    const float* cb = cosm + (size_t)b * S_ * S_;
    float acc = 0.f;
    for (int i = 0; i < S_; i++) acc += cb[i * S_ + j] * src[((size_t)b * S_ + i) * H_ + h];
    outp[((size_t)b * S_ + j) * H_ + h] = acc / dsum[b * S_ + j];
}

__global__ void attn_mean_j_kernel(const float* __restrict__ cosm, const float* __restrict__ src,
                                   const float* __restrict__ dsum, float* __restrict__ outp) {
    int b = blockIdx.y, i = blockIdx.x, h = threadIdx.x;
    if (h >= H_) return;
    const float* cb = cosm + (size_t)b * S_ * S_;
    float acc = 0.f;
    for (int j = 0; j < S_; j++) acc += cb[i * S_ + j] * src[((size_t)b * S_ + j) * H_ + h];
    outp[((size_t)b * S_ + i) * H_ + h] = acc / dsum[b * S_ + i];
}

__global__ void attn_max_i_kernel(const float* __restrict__ cosm, const float* __restrict__ src,
                                  float* __restrict__ outp) {
    int b = blockIdx.y, j = blockIdx.x, h = threadIdx.x;
    if (h >= H_) return;
    const float* cb = cosm + (size_t)b * S_ * S_;
    float m = -INFINITY;
    for (int i = 0; i < S_; i++) m = fmaxf(m, cb[i * S_ + j] * src[((size_t)b * S_ + i) * H_ + h]);
    outp[((size_t)b * S_ + j) * H_ + h] = m;
}

__global__ void attn_max_j_kernel(const float* __restrict__ cosm, const float* __restrict__ src,
                                  float* __restrict__ outp) {
    int b = blockIdx.y, i = blockIdx.x, h = threadIdx.x;
    if (h >= H_) return;
    const float* cb = cosm + (size_t)b * S_ * S_;
    float m = -INFINITY;
    for (int j = 0; j < S_; j++) m = fmaxf(m, cb[i * S_ + j] * src[((size_t)b * S_ + j) * H_ + h]);
    outp[((size_t)b * S_ + i) * H_ + h] = m;
}

__global__ void pair_max_j_kernel(const float* __restrict__ pair, float* __restrict__ vout, int off) {
    int b = blockIdx.y, i = blockIdx.x, l = threadIdx.x;
    if (l >= L_) return;
    const float* p = pair + (((size_t)b * L_ + l) * S_ + i) * S_;
    float m = -INFINITY;
    for (int j = 0; j < S_; j++) m = fmaxf(m, p[j]);
    vout[((size_t)b * S_ + i) * VD_ + off + l] = m;
}

__global__ void pair_max_i_kernel(const float* __restrict__ pair, float* __restrict__ vout, int off) {
    int b = blockIdx.y, j = blockIdx.x, l = threadIdx.x;
    if (l >= L_) return;
    const float* p = pair + ((size_t)b * L_ + l) * S_ * S_ + j;
    float m = -INFINITY;
    for (int i = 0; i < S_; i++) m = fmaxf(m, p[i * S_]);
    vout[((size_t)b * S_ + j) * VD_ + off + l] = m;
}

__global__ void pred1_kernel(const float* __restrict__ hc, const float* __restrict__ W1,
                             const float* __restrict__ b1, float* __restrict__ x) {
    int b = blockIdx.x;
    __shared__ float mv[G4_];
    for (int k = threadIdx.x; k < G4_; k += blockDim.x) {
        int st = k / H_, m = k % H_;
        mv[k] = hc[(size_t)(st * 3) * B_ * H_ + (size_t)b * H_ + m];   // final h lives in slot 0
    }
    __syncthreads();
    int j = threadIdx.x;
    if (j < 600) {
        const float* w = W1 + (size_t)j * G4_;
        float acc = b1[j];
        for (int k = 0; k < G4_; k++) acc += mv[k] * w[k];
        x[b * 600 + j] = tanhf(acc);
    }
}

__global__ void pred2_kernel(const float* __restrict__ x, const float* __restrict__ W2,
                             const float* __restrict__ b2, float* __restrict__ out) {
    int b = threadIdx.x;
    if (b >= B_) return;
    float z0 = b2[0], z1 = b2[1];
    for (int k = 0; k < 600; k++) {
        float v = x[b * 600 + k];
        z0 += v * W2[k];
        z1 += v * W2[600 + k];
    }
    float m = fmaxf(z0, z1);
    float lse = m + logf(expf(z0 - m) + expf(z1 - m));
    out[b * 2 + 0] = z0 - lse;
    out[b * 2 + 1] = z1 - lse;
}

// ------------------------------- host ----------------------------------------

extern "C" void kernel_launch(void* const* d_in, const int* in_sizes, int n_in,
                              void* d_out, int out_size) {
    const float* emb       = (const float*)d_in[0];
    const float* ctx_Wih_f = (const float*)d_in[1];
    const float* ctx_Whh_f = (const float*)d_in[2];
    const float* ctx_b_f   = (const float*)d_in[3];
    const float* ctx_Wih_b = (const float*)d_in[4];
    const float* ctx_Whh_b = (const float*)d_in[5];
    const float* ctx_b_b   = (const float*)d_in[6];
    const float* agg_Wih_f = (const float*)d_in[7];
    const float* agg_Whh_f = (const float*)d_in[8];
    const float* agg_b_f   = (const float*)d_in[9];
    const float* agg_Wih_b = (const float*)d_in[10];
    const float* agg_Whh_b = (const float*)d_in[11];
    const float* agg_b_b   = (const float*)d_in[12];
    const float* W_full_f  = (const float*)d_in[13];
    const float* W_full_b  = (const float*)d_in[14];
    const float* W_mp_f    = (const float*)d_in[15];
    const float* W_mp_b    = (const float*)d_in[16];
    const float* W_attn_f  = (const float*)d_in[17];
    const float* W_mattn_f = (const float*)d_in[18];
    const float* pred_W1   = (const float*)d_in[19];
    const float* pred_b1   = (const float*)d_in[20];
    const float* pred_W2   = (const float*)d_in[21];
    const float* pred_b2   = (const float*)d_in[22];
    const int*   sa        = (const int*)d_in[23];
    const int*   sb        = (const int*)d_in[24];
    float* out = (float*)d_out;

    float *s1, *s2, *xg, *o, *on, *hc, *pair, *cosm, *rsum, *csum, *meanb, *maxb, *vbuf, *x1;
    cudaGetSymbolAddress((void**)&s1,   g_s1);
    cudaGetSymbolAddress((void**)&s2,   g_s2);
    cudaGetSymbolAddress((void**)&xg,   g_xg);
    cudaGetSymbolAddress((void**)&o,    g_o);
    cudaGetSymbolAddress((void**)&on,   g_on);
    cudaGetSymbolAddress((void**)&hc,   g_hc);
    cudaGetSymbolAddress((void**)&pair, g_pair);
    cudaGetSymbolAddress((void**)&cosm, g_cos);
    cudaGetSymbolAddress((void**)&rsum, g_rsum);
    cudaGetSymbolAddress((void**)&csum, g_csum);
    cudaGetSymbolAddress((void**)&meanb,g_mean);
    cudaGetSymbolAddress((void**)&maxb, g_maxv);
    cudaGetSymbolAddress((void**)&vbuf, g_v);
    cudaGetSymbolAddress((void**)&x1,   g_x1);

    const size_t SLC = (size_t)BS_ * H_;          // per-stream ctx output slice
    const size_t XSL = (size_t)BS_ * G4_;         // per-stream xg slice
    const size_t CSS = (size_t)B_ * S_ * S_;      // cos matrix size
    const size_t PSS = (size_t)B_ * L_ * S_ * S_; // pair tensor size
    const long   SH  = (long)S_ * H_;

    // 1) embedding gather
    gather_emb_kernel<<<BS_, 128>>>(emb, sa, sb, s1, s2);

    // 2) context gate precompute (4 GEMMs)
    dim3 gb((G4_ + 63) / 64, BS_ / 64);
    gemm_bias_kernel<<<gb, 256>>>(s1, ctx_Wih_f, ctx_b_f, xg + 0 * XSL, BS_, G4_, D_);
    gemm_bias_kernel<<<gb, 256>>>(s1, ctx_Wih_b, ctx_b_b, xg + 1 * XSL, BS_, G4_, D_);
    gemm_bias_kernel<<<gb, 256>>>(s2, ctx_Wih_f, ctx_b_f, xg + 2 * XSL, BS_, G4_, D_);
    gemm_bias_kernel<<<gb, 256>>>(s2, ctx_Wih_b, ctx_b_b, xg + 3 * XSL, BS_, G4_, D_);

    // 3) context BiLSTM (4 streams fused per step)
    int hcN = 4 * 3 * B_ * H_;
    zero_kernel<<<(hcN + 255) / 256, 256>>>(hc, hcN);
    for (int s = 0; s < S_; s++)
        lstm_step_kernel<<<dim3(25, 4), 384>>>(xg, ctx_Whh_f, ctx_Whh_b, hc, o, s);

    float* s1f = o;            float* s1b = o + SLC;
    float* s2f = o + 2 * SLC;  float* s2b = o + 3 * SLC;
    float* s1fn = on;          float* s1bn = on + SLC;
    float* s2fn = on + 2*SLC;  float* s2bn = on + 3 * SLC;
    float* v1 = vbuf;          float* v2 = vbuf + (size_t)BS_ * VD_;

    // 4) normalized copies
    normalize_kernel<<<(4 * BS_ * 32 + 255) / 256, 256>>>(o, on, 4 * BS_);

    // 5) full matching
    dim3 gfm(S_, B_);
    full_match_kernel<<<gfm, 64>>>(s1f, s2f + (size_t)(S_ - 1) * H_, SH, 0, W_full_f, v1, 0);
    full_match_kernel<<<gfm, 64>>>(s1b, s2b,                         SH, 0, W_full_b, v1, 80);
    full_match_kernel<<<gfm, 64>>>(s2f, s1f + (size_t)(S_ - 1) * H_, SH, 0, W_full_f, v2, 0);
    full_match_kernel<<<gfm, 64>>>(s2b, s1b,                         SH, 0, W_full_b, v2, 80);

    // 6) pairwise (maxpool) matching
    pairwise_kernel<<<dim3(L_, B_), 256>>>(s1fn, s2bn, W_mp_f, pair);
    pairwise_kernel<<<dim3(L_, B_), 256>>>(s1bn, s2bn, W_mp_b, pair + PSS);
    pair_max_j_kernel<<<gfm, 32>>>(pair,        v1, 20);
    pair_max_j_kernel<<<gfm, 32>>>(pair + PSS,  v1, 100);
    pair_max_i_kernel<<<gfm, 32>>>(pair,        v2, 20);
    pair_max_i_kernel<<<gfm, 32>>>(pair + PSS,  v2, 100);

    // 7) cosine matrices + sums
    cosine_kernel<<<B_, 256>>>(s1fn, s2fn, cosm);
    cosine_kernel<<<B_, 256>>>(s1bn, s2bn, cosm + CSS);
    cos_sums_kernel<<<B_, S_>>>(cosm,       rsum,          csum);
    cos_sums_kernel<<<B_, S_>>>(cosm + CSS, rsum + B_ * S_, csum + B_ * S_);

    // 8) attentive mean / max vectors (all use s1f / s2f per reference)
    attn_mean_j_kernel<<<gfm, 320>>>(cosm,       s2f, csum,           meanb + 0 * SLC); // mean_s1_f
    attn_mean_j_kernel<<<gfm, 320>>>(cosm + CSS, s2f, csum + B_ * S_, meanb + 1 * SLC); // mean_s1_b
    attn_mean_i_kernel<<<gfm, 320>>>(cosm,       s1f, rsum,           meanb + 2 * SLC); // mean_s2_f
    attn_mean_i_kernel<<<gfm, 320>>>(cosm + CSS, s1f, rsum + B_ * S_, meanb + 3 * SLC); // mean_s2_b
    attn_max_j_kernel <<<gfm, 320>>>(cosm,       s2f, maxb + 0 * SLC);                  // max_s1_f
    attn_max_j_kernel <<<gfm, 320>>>(cosm + CSS, s2f, maxb + 1 * SLC);                  // max_s1_b
    attn_max_i_kernel <<<gfm, 320>>>(cosm,       s1f, maxb + 2 * SLC);                  // max_s2_f
    attn_max_i_kernel <<<gfm, 320>>>(cosm + CSS, s1f, maxb + 3 * SLC);                  // max_s2_b

    // 9) attentive / max-attentive full matches
    full_match_kernel<<<gfm, 64>>>(s1f, meanb + 0 * SLC, SH, H_, W_attn_f,  v1, 40);
    full_match_kernel<<<gfm, 64>>>(s1b, meanb + 1 * SLC, SH, H_, W_attn_f,  v1, 120);
    full_match_kernel<<<gfm, 64>>>(s2f, meanb + 2 * SLC, SH, H_, W_attn_f,  v2, 40);
    full_match_kernel<<<gfm, 64>>>(s2b, meanb + 3 * SLC, SH, H_, W_attn_f,  v2, 120);
    full_match_kernel<<<gfm, 64>>>(s1f, maxb + 0 * SLC, SH, H_, W_mattn_f, v1, 60);
    full_match_kernel<<<gfm, 64>>>(s1b, maxb + 1 * SLC, SH, H_, W_mattn_f, v1, 140);
    full_match_kernel<<<gfm, 64>>>(s2f, maxb + 2 * SLC, SH, H_, W_mattn_f, v2, 60);
    full_match_kernel<<<gfm, 64>>>(s2b, maxb + 3 * SLC, SH, H_, W_mattn_f, v2, 140);

    // 10) aggregation gate precompute (4 GEMMs, reuse xg)
    gemm_bias_kernel<<<gb, 256>>>(v1, agg_Wih_f, agg_b_f, xg + 0 * XSL, BS_, G4_, VD_);
    gemm_bias_kernel<<<gb, 256>>>(v1, agg_Wih_b, agg_b_b, xg + 1 * XSL, BS_, G4_, VD_);
    gemm_bias_kernel<<<gb, 256>>>(v2, agg_Wih_f, agg_b_f, xg + 2 * XSL, BS_, G4_, VD_);
    gemm_bias_kernel<<<gb, 256>>>(v2, agg_Wih_b, agg_b_b, xg + 3 * XSL, BS_, G4_, VD_);

    // 11) aggregation BiLSTM (only final h needed)
    zero_kernel<<<(hcN + 255) / 256, 256>>>(hc, hcN);
    for (int s = 0; s < S_; s++)
        lstm_step_kernel<<<dim3(25, 4), 384>>>(xg, agg_Whh_f, agg_Whh_b, hc, (float*)0, s);

    // 12) prediction head + log_softmax
    pred1_kernel<<<B_, 640>>>(hc, pred_W1, pred_b1, x1);
    pred2_kernel<<<1, 32>>>(x1, pred_W2, pred_b2, out);
}

// round 2
// speedup vs baseline: 1.7250x; 1.7250x over previous
#include <cuda_runtime.h>
#include <math.h>

#define B_   32
#define S_   64
#define H_   300
#define D_   300
#define L_   20
#define BS_  2048          // B*S
#define G4_  1200          // 4*H
#define VD_  160           // 8*L
#define EPSV 1e-8f
#define LSTM_BLOCKS 100

// ------------------------- scratch (static device globals) -------------------
__device__ float g_s1[BS_*D_];
__device__ float g_s2[BS_*D_];
__device__ float g_xg[4*BS_*G4_];        // gate preactivations, reused ctx->agg
__device__ float g_o[4*BS_*H_];          // ctx outputs: s1f,s1b,s2f,s2b
__device__ float g_on[4*BS_*H_];         // row-normalized copies
__device__ float g_hT[2*4*H_*B_];        // transposed h state [slot][st][m][b]
__device__ float g_pair[2*B_*L_*S_*S_];  // [which][B][L][S][S]
__device__ float g_cos[2*B_*S_*S_];
__device__ float g_rsum[2*B_*S_];        // sum over i (axis=1)
__device__ float g_csum[2*B_*S_];        // sum over j (axis=2)
__device__ float g_mean[4*BS_*H_];
__device__ float g_maxv[4*BS_*H_];
__device__ float g_v[2*BS_*VD_];         // v1, v2
__device__ float g_x1[B_*600];
__device__ unsigned g_bar;

// ------------------------------- kernels -------------------------------------

__global__ void zero_kernel(float* p, int n) {
    int i = blockIdx.x * blockDim.x + threadIdx.x;
    if (i < n) p[i] = 0.f;
}

__global__ void reset_bar_kernel() { g_bar = 0u; }

__global__ void gather_emb_kernel(const float* __restrict__ emb,
                                  const int* __restrict__ ia, const int* __restrict__ ib,
                                  float* __restrict__ s1, float* __restrict__ s2) {
    int row = blockIdx.x;
    int a = ia[row], b = ib[row];
    for (int k = threadIdx.x; k < D_; k += blockDim.x) {
        s1[(size_t)row * D_ + k] = emb[(size_t)a * D_ + k];
        s2[(size_t)row * D_ + k] = emb[(size_t)b * D_ + k];
    }
}

// C[M,N] = A[M,K] @ W[N,K]^T + bias[N]
__global__ void gemm_bias_kernel(const float* __restrict__ A, const float* __restrict__ W,
                                 const float* __restrict__ bias, float* __restrict__ C,
                                 int M, int N, int K) {
    __shared__ float As[8][68];
    __shared__ float Bs[8][68];
    int tid = threadIdx.x;
    int ti = tid >> 4, tj = tid & 15;
    int m0 = blockIdx.y * 64, n0 = blockIdx.x * 64;
    float acc[4][4] = {};
    for (int k0 = 0; k0 < K; k0 += 8) {
        #pragma unroll
        for (int r = 0; r < 2; r++) {
            int idx = tid + r * 256;
            int row = idx >> 3, col = idx & 7;
            int kk = k0 + col;
            int m = m0 + row;
            int n = n0 + row;
            As[col][row] = (kk < K && m < M) ? A[(size_t)m * K + kk] : 0.f;
            Bs[col][row] = (kk < K && n < N) ? W[(size_t)n * K + kk] : 0.f;
        }
        __syncthreads();
        #pragma unroll
        for (int kk = 0; kk < 8; kk++) {
            float4 a4 = *(const float4*)&As[kk][ti * 4];
            float4 b4 = *(const float4*)&Bs[kk][tj * 4];
            float av[4] = {a4.x, a4.y, a4.z, a4.w};
            float bv[4] = {b4.x, b4.y, b4.z, b4.w};
            #pragma unroll
            for (int r = 0; r < 4; r++)
                #pragma unroll
                for (int c = 0; c < 4; c++)
                    acc[r][c] += av[r] * bv[c];
        }
        __syncthreads();
    }
    #pragma unroll
    for (int r = 0; r < 4; r++) {
        int m = m0 + ti * 4 + r;
        if (m >= M) continue;
        #pragma unroll
        for (int c = 0; c < 4; c++) {
            int n = n0 + tj * 4 + c;
            if (n < N) C[(size_t)m * N + n] = acc[r][c] + bias[n];
        }
    }
}

// ----------------------- persistent BiLSTM scan ------------------------------
// 100 blocks (4 streams x 25 chunks of 12 m), 384 threads, all co-resident.
// W chunk cached in smem; h kept transposed [m][b]; c in registers; software
// grid barrier between steps.
__global__ void __launch_bounds__(384, 1)
lstm_scan_kernel(const float* __restrict__ xg,
                 const float* __restrict__ Whf, const float* __restrict__ Whb,
                 float* __restrict__ hT, float* __restrict__ ys) {
    extern __shared__ float sm[];
    float*  w_sm = sm;                       // [48][300]
    float4* h4   = (float4*)(sm + 14400);    // [300][32] floats = [300][8] float4
    float*  red  = sm + 14400 + 9600;        // [384][16]

    int tid = threadIdx.x;
    int st = blockIdx.x / 25;
    int chunk = blockIdx.x - st * 25;
    int m0 = chunk * 12;
    const float* W = (st & 1) ? Whb : Whf;

    // load W chunk: rows (g*300 + m0 + r) for g in 0..3, r in 0..11
    for (int idx = tid; idx < 48 * 300; idx += 384) {
        int rr = idx / 300, k = idx - rr * 300;
        int g = rr / 12, r = rr - g * 12;
        w_sm[idx] = W[(size_t)(g * 300 + m0 + r) * 300 + k];
    }

    int kq  = tid / 96;
    int rem = tid - kq * 96;
    int rq  = rem >> 3;
    int bq  = rem & 7;
    int m   = m0 + rq;
    int rev = st & 1;
    float cstate[4] = {0.f, 0.f, 0.f, 0.f};
    const float* wb = w_sm + rq * 300;

    size_t xbase[4];
    #pragma unroll
    for (int bi = 0; bi < 4; bi++)
        xbase[bi] = ((size_t)st * BS_ + (size_t)(bq * 4 + bi) * S_) * G4_;

    for (int s = 0; s < S_; s++) {
        if (s) {
            __threadfence();
            __syncthreads();
            if (tid == 0) {
                atomicAdd(&g_bar, 1u);
                unsigned target = (unsigned)s * LSTM_BLOCKS;
                while (*(volatile unsigned*)&g_bar < target) { }
            }
            __syncthreads();
            __threadfence();
        }
        // stage h (transposed layout, linear copy -> coalesced + conflict-free)
        const float4* hin = (const float4*)(hT + (size_t)((s & 1) * 4 + st) * (H_ * B_));
        for (int idx = tid; idx < 2400; idx += 384) h4[idx] = hin[idx];
        __syncthreads();

        float acc[16];
        #pragma unroll
        for (int q = 0; q < 16; q++) acc[q] = 0.f;

        for (int j = kq; j < 75; j += 4) {
            int k = j * 4;
            float4 h0 = h4[k * 8 + bq];
            float4 h1 = h4[k * 8 + 8 + bq];
            float4 h2 = h4[k * 8 + 16 + bq];
            float4 h3 = h4[k * 8 + 24 + bq];
            #pragma unroll
            for (int g = 0; g < 4; g++) {
                float4 w4 = *(const float4*)(wb + g * 3600 + k);
                float* A = acc + g * 4;
                A[0] = fmaf(w4.x, h0.x, A[0]); A[0] = fmaf(w4.y, h1.x, A[0]);
                A[0] = fmaf(w4.z, h2.x, A[0]); A[0] = fmaf(w4.w, h3.x, A[0]);
                A[1] = fmaf(w4.x, h0.y, A[1]); A[1] = fmaf(w4.y, h1.y, A[1]);
                A[1] = fmaf(w4.z, h2.y, A[1]); A[1] = fmaf(w4.w, h3.y, A[1]);
                A[2] = fmaf(w4.x, h0.z, A[2]); A[2] = fmaf(w4.y, h1.z, A[2]);
                A[2] = fmaf(w4.z, h2.z, A[2]); A[2] = fmaf(w4.w, h3.z, A[2]);
                A[3] = fmaf(w4.x, h0.w, A[3]); A[3] = fmaf(w4.y, h1.w, A[3]);
                A[3] = fmaf(w4.z, h2.w, A[3]); A[3] = fmaf(w4.w, h3.w, A[3]);
            }
        }
        {
            float* rp = red + tid * 16;
            #pragma unroll
            for (int q = 0; q < 16; q++) rp[q] = acc[q];
        }
        __syncthreads();
        if (tid < 96) {
            int t = rev ? (S_ - 1 - s) : s;
            const float* r0 = red + tid * 16;
            const float* r1 = r0 + 96 * 16;
            const float* r2 = r1 + 96 * 16;
            const float* r3 = r2 + 96 * 16;
            float hnv[4];
            #pragma unroll
            for (int bi = 0; bi < 4; bi++) {
                float si = r0[0*4+bi] + r1[0*4+bi] + r2[0*4+bi] + r3[0*4+bi];
                float sf = r0[1*4+bi] + r1[1*4+bi] + r2[1*4+bi] + r3[1*4+bi];
                float sg = r0[2*4+bi] + r1[2*4+bi] + r2[2*4+bi] + r3[2*4+bi];
                float so = r0[3*4+bi] + r1[3*4+bi] + r2[3*4+bi] + r3[3*4+bi];
                const float* xr = xg + xbase[bi] + (size_t)t * G4_;
                float ai = si + xr[m];
                float af = sf + xr[H_ + m];
                float ag = sg + xr[2 * H_ + m];
                float ao = so + xr[3 * H_ + m];
                float ii = 1.f / (1.f + expf(-ai));
                float ff = 1.f / (1.f + expf(-af));
                float gg = tanhf(ag);
                float oo = 1.f / (1.f + expf(-ao));
                float cn = ff * cstate[bi] + ii * gg;
                cstate[bi] = cn;
                float hn = oo * tanhf(cn);
                hnv[bi] = hn;
                if (ys) ys[((size_t)(st * B_ + (bq * 4 + bi)) * S_ + t) * H_ + m] = hn;
            }
            float* hw = hT + (size_t)(((s + 1) & 1) * 4 + st) * (H_ * B_) + m * B_ + bq * 4;
            *(float4*)hw = make_float4(hnv[0], hnv[1], hnv[2], hnv[3]);
        }
    }
}

__global__ void normalize_kernel(const float* __restrict__ in, float* __restrict__ out, int nrows) {
    int warp = (blockIdx.x * blockDim.x + threadIdx.x) >> 5;
    int lane = threadIdx.x & 31;
    if (warp >= nrows) return;
    const float* r = in + (size_t)warp * H_;
    float ss = 0.f;
    for (int k = lane; k < H_; k += 32) { float v = r[k]; ss += v * v; }
    #pragma unroll
    for (int o = 16; o; o >>= 1) ss += __shfl_xor_sync(0xffffffffu, ss, o);
    float inv = rsqrtf(ss);
    float* w = out + (size_t)warp * H_;
    for (int k = lane; k < H_; k += 32) w[k] = r[k] * inv;
}

// ----------------------- batched full match ----------------------------------
struct FMArg { const float* a; const float* c; long bs; long ss; const float* W; float* vout; int off; int pad; };
struct FMArgs16 { FMArg e[16]; };

__global__ void full_match_batched(FMArgs16 args) {
    FMArg A = args.e[blockIdx.z];
    int b = blockIdx.y, sIdx = blockIdx.x;
    __shared__ float a_sm[H_], c_sm[H_];
    const float* a = A.a + ((size_t)b * S_ + sIdx) * H_;
    const float* c = A.c + (size_t)b * A.bs + (size_t)sIdx * A.ss;
    for (int k = threadIdx.x; k < H_; k += blockDim.x) { a_sm[k] = a[k]; c_sm[k] = c[k]; }
    __syncthreads();
    int l = threadIdx.x;
    if (l < L_) {
        const float* w = A.W + l * H_;
        float num = 0.f, na = 0.f, nc = 0.f;
        for (int k = 0; k < H_; k++) {
            float wv = w[k]; float w2 = wv * wv;
            float av = a_sm[k], cv = c_sm[k];
            num += w2 * av * cv; na += w2 * av * av; nc += w2 * cv * cv;
        }
        float d = fmaxf(sqrtf(na), EPSV) * fmaxf(sqrtf(nc), EPSV);
        A.vout[((size_t)b * S_ + sIdx) * VD_ + A.off + l] = num / d;
    }
}

// m_pair[b,l,i,j] = sum_h W2[l,h] s1n[b,i,h] s2n[b,j,h]  (inputs pre-normalized)
__global__ void pairwise_kernel(const float* __restrict__ s1n, const float* __restrict__ s2n,
                                const float* __restrict__ Wm, float* __restrict__ outp) {
    int l = blockIdx.x, b = blockIdx.y;
    __shared__ float s1w[60][64], s2c[60][64];
    const float* w = Wm + l * H_;
    int tid = threadIdx.x;
    int ti = tid >> 4, tj = tid & 15;
    float acc[4][4] = {};
    for (int h0 = 0; h0 < H_; h0 += 60) {
        for (int idx = tid; idx < 64 * 60; idx += 256) {
            int i = idx / 60, hh = idx % 60;
            float wv = w[h0 + hh];
            size_t gi = ((size_t)b * S_ + i) * H_ + h0 + hh;
            s1w[hh][i] = s1n[gi] * wv * wv;
            s2c[hh][i] = s2n[gi];
        }
        __syncthreads();
        #pragma unroll 4
        for (int hh = 0; hh < 60; hh++) {
            float4 a4 = *(const float4*)&s1w[hh][ti * 4];
            float4 b4 = *(const float4*)&s2c[hh][tj * 4];
            float av[4] = {a4.x, a4.y, a4.z, a4.w};
            float bv[4] = {b4.x, b4.y, b4.z, b4.w};
            #pragma unroll
            for (int r = 0; r < 4; r++)
                #pragma unroll
                for (int c = 0; c < 4; c++)
                    acc[r][c] += av[r] * bv[c];
        }
        __syncthreads();
    }
    float* o = outp + ((size_t)b * L_ + l) * S_ * S_;
    #pragma unroll
    for (int r = 0; r < 4; r++)
        #pragma unroll
        for (int c = 0; c < 4; c++)
            o[(ti * 4 + r) * S_ + tj * 4 + c] = acc[r][c];
}

__global__ void cosine_kernel(const float* __restrict__ an, const float* __restrict__ bn,
                              float* __restrict__ outp) {
    int b = blockIdx.x;
    __shared__ float s1c[60][64], s2c[60][64];
    int tid = threadIdx.x;
    int ti = tid >> 4, tj = tid & 15;
    float acc[4][4] = {};
    for (int h0 = 0; h0 < H_; h0 += 60) {
        for (int idx = tid; idx < 64 * 60; idx += 256) {
            int i = idx / 60, hh = idx % 60;
            size_t gi = ((size_t)b * S_ + i) * H_ + h0 + hh;
            s1c[hh][i] = an[gi];
            s2c[hh][i] = bn[gi];
        }
        __syncthreads();
        #pragma unroll 4
        for (int hh = 0; hh < 60; hh++) {
            float4 a4 = *(const float4*)&s1c[hh][ti * 4];
            float4 b4 = *(const float4*)&s2c[hh][tj * 4];
            float av[4] = {a4.x, a4.y, a4.z, a4.w};
            float bv[4] = {b4.x, b4.y, b4.z, b4.w};
            #pragma unroll
            for (int r = 0; r < 4; r++)
                #pragma unroll
                for (int c = 0; c < 4; c++)
                    acc[r][c] += av[r] * bv[c];
        }
        __syncthreads();
    }
    float* o = outp + (size_t)b * S_ * S_;
    #pragma unroll
    for (int r = 0; r < 4; r++)
        #pragma unroll
        for (int c = 0; c < 4; c++)
            o[(ti * 4 + r) * S_ + tj * 4 + c] = acc[r][c];
}

__global__ void cos_sums_kernel(const float* __restrict__ cosm,
                                float* __restrict__ rsum, float* __restrict__ csum) {
    int b = blockIdx.x, t = threadIdx.x;
    const float* cb = cosm + (size_t)b * S_ * S_;
    float sj = 0.f, si = 0.f;
    for (int k = 0; k < S_; k++) { sj += cb[t * S_ + k]; si += cb[k * S_ + t]; }
    csum[b * S_ + t] = sj;
    rsum[b * S_ + t] = si;
}

// Fused attentive mean+max, f+b dirs, output index i, reduce over j. src = s2f.
__global__ void attn_row_kernel(const float* __restrict__ cosf, const float* __restrict__ cosb,
                                const float* __restrict__ src,
                                const float* __restrict__ sumf, const float* __restrict__ sumb,
                                float* __restrict__ mf_o, float* __restrict__ mb_o,
                                float* __restrict__ xf_o, float* __restrict__ xb_o) {
    __shared__ float cf_sm[8 * 64], cb_sm[8 * 64];
    int b = blockIdx.y, i0 = blockIdx.x * 8;
    int tid = threadIdx.x;
    for (int idx = tid; idx < 512; idx += 320) {
        int q = idx >> 6, j = idx & 63;
        cf_sm[idx] = cosf[(size_t)b * 4096 + (i0 + q) * 64 + j];
        cb_sm[idx] = cosb[(size_t)b * 4096 + (i0 + q) * 64 + j];
    }
    __syncthreads();
    int h = tid;
    if (h >= H_) return;
    float accf[8] = {}, accb[8] = {}, mxf[8], mxb[8];
    #pragma unroll
    for (int q = 0; q < 8; q++) { mxf[q] = -INFINITY; mxb[q] = -INFINITY; }
    for (int j4 = 0; j4 < 64; j4 += 4) {
        float v0 = src[((size_t)b * 64 + j4 + 0) * H_ + h];
        float v1 = src[((size_t)b * 64 + j4 + 1) * H_ + h];
        float v2 = src[((size_t)b * 64 + j4 + 2) * H_ + h];
        float v3 = src[((size_t)b * 64 + j4 + 3) * H_ + h];
        #pragma unroll
        for (int q = 0; q < 8; q++) {
            float4 c4 = *(const float4*)&cf_sm[q * 64 + j4];
            float4 d4 = *(const float4*)&cb_sm[q * 64 + j4];
            float p;
            p = c4.x * v0; accf[q] += p; mxf[q] = fmaxf(mxf[q], p);
            p = c4.y * v1; accf[q] += p; mxf[q] = fmaxf(mxf[q], p);
            p = c4.z * v2; accf[q] += p; mxf[q] = fmaxf(mxf[q], p);
            p = c4.w * v3; accf[q] += p; mxf[q] = fmaxf(mxf[q], p);
            p = d4.x * v0; accb[q] += p; mxb[q] = fmaxf(mxb[q], p);
            p = d4.y * v1; accb[q] += p; mxb[q] = fmaxf(mxb[q], p);
            p = d4.z * v2; accb[q] += p; mxb[q] = fmaxf(mxb[q], p);
            p = d4.w * v3; accb[q] += p; mxb[q] = fmaxf(mxb[q], p);
        }
    }
    #pragma unroll
    for (int q = 0; q < 8; q++) {
        int i = i0 + q;
        size_t o = ((size_t)b * 64 + i) * H_ + h;
        mf_o[o] = accf[q] / sumf[b * 64 + i];
        mb_o[o] = accb[q] / sumb[b * 64 + i];
        xf_o[o] = mxf[q]; xb_o[o] = mxb[q];
    }
}

// Fused attentive mean+max, output index j, reduce over i. src = s1f.
__global__ void attn_col_kernel(const float* __restrict__ cosf, const float* __restrict__ cosb,
                                const float* __restrict__ src,
                                const float* __restrict__ sumf, const float* __restrict__ sumb,
                                float* __restrict__ mf_o, float* __restrict__ mb_o,
                                float* __restrict__ xf_o, float* __restrict__ xb_o) {
    __shared__ float cf_sm[8 * 64], cb_sm[8 * 64];   // transposed: [q][i]
    int b = blockIdx.y, j0 = blockIdx.x * 8;
    int tid = threadIdx.x;
    for (int idx = tid; idx < 512; idx += 320) {
        int q = idx >> 6, i = idx & 63;
        cf_sm[idx] = cosf[(size_t)b * 4096 + i * 64 + j0 + q];
        cb_sm[idx] = cosb[(size_t)b * 4096 + i * 64 + j0 + q];
    }
    __syncthreads();
    int h = tid;
    if (h >= H_) return;
    float accf[8] = {}, accb[8] = {}, mxf[8], mxb[8];
    #pragma unroll
    for (int q = 0; q < 8; q++) { mxf[q] = -INFINITY; mxb[q] = -INFINITY; }
    for (int i4 = 0; i4 < 64; i4 += 4) {
        float v0 = src[((size_t)b * 64 + i4 + 0) * H_ + h];
        float v1 = src[((size_t)b * 64 + i4 + 1) * H_ + h];
        float v2 = src[((size_t)b * 64 + i4 + 2) * H_ + h];
        float v3 = src[((size_t)b * 64 + i4 + 3) * H_ + h];
        #pragma unroll
        for (int q = 0; q < 8; q++) {
            float4 c4 = *(const float4*)&cf_sm[q * 64 + i4];
            float4 d4 = *(const float4*)&cb_sm[q * 64 + i4];
            float p;
            p = c4.x * v0; accf[q] += p; mxf[q] = fmaxf(mxf[q], p);
            p = c4.y * v1; accf[q] += p; mxf[q] = fmaxf(mxf[q], p);
            p = c4.z * v2; accf[q] += p; mxf[q] = fmaxf(mxf[q], p);
            p = c4.w * v3; accf[q] += p; mxf[q] = fmaxf(mxf[q], p);
            p = d4.x * v0; accb[q] += p; mxb[q] = fmaxf(mxb[q], p);
            p = d4.y * v1; accb[q] += p; mxb[q] = fmaxf(mxb[q], p);
            p = d4.z * v2; accb[q] += p; mxb[q] = fmaxf(mxb[q], p);
            p = d4.w * v3; accb[q] += p; mxb[q] = fmaxf(mxb[q], p);
        }
    }
    #pragma unroll
    for (int q = 0; q < 8; q++) {
        int j = j0 + q;
        size_t o = ((size_t)b * 64 + j) * H_ + h;
        mf_o[o] = accf[q] / sumf[b * 64 + j];
        mb_o[o] = accb[q] / sumb[b * 64 + j];
        xf_o[o] = mxf[q]; xb_o[o] = mxb[q];
    }
}

__global__ void pair_max_j_kernel(const float* __restrict__ pair, float* __restrict__ vout, int off) {
    int b = blockIdx.y, i = blockIdx.x, l = threadIdx.x;
    if (l >= L_) return;
    const float* p = pair + (((size_t)b * L_ + l) * S_ + i) * S_;
    float m = -INFINITY;
    for (int j = 0; j < S_; j++) m = fmaxf(m, p[j]);
    vout[((size_t)b * S_ + i) * VD_ + off + l] = m;
}

__global__ void pair_max_i_kernel(const float* __restrict__ pair, float* __restrict__ vout, int off) {
    int b = blockIdx.y, j = blockIdx.x, l = threadIdx.x;
    if (l >= L_) return;
    const float* p = pair + ((size_t)b * L_ + l) * S_ * S_ + j;
    float m = -INFINITY;
    for (int i = 0; i < S_; i++) m = fmaxf(m, p[i * S_]);
    vout[((size_t)b * S_ + j) * VD_ + off + l] = m;
}

__global__ void pred1_kernel(const float* __restrict__ hT, const float* __restrict__ W1,
                             const float* __restrict__ b1, float* __restrict__ x) {
    int b = blockIdx.x;
    __shared__ float mv[G4_];
    for (int k = threadIdx.x; k < G4_; k += blockDim.x) {
        int st = k / H_, m = k % H_;
        mv[k] = hT[(size_t)st * (H_ * B_) + m * B_ + b];   // final h in slot 0
    }
    __syncthreads();
    int j = threadIdx.x;
    if (j < 600) {
        const float* w = W1 + (size_t)j * G4_;
        float acc = b1[j];
        for (int k = 0; k < G4_; k++) acc += mv[k] * w[k];
        x[b * 600 + j] = tanhf(acc);
    }
}

__global__ void pred2_kernel(const float* __restrict__ x, const float* __restrict__ W2,
                             const float* __restrict__ b2, float* __restrict__ out) {
    int b = threadIdx.x;
    if (b >= B_) return;
    float z0 = b2[0], z1 = b2[1];
    for (int k = 0; k < 600; k++) {
        float v = x[b * 600 + k];
        z0 += v * W2[k];
        z1 += v * W2[600 + k];
    }
    float m = fmaxf(z0, z1);
    float lse = m + logf(expf(z0 - m) + expf(z1 - m));
    out[b * 2 + 0] = z0 - lse;
    out[b * 2 + 1] = z1 - lse;
}

// ------------------------------- host ----------------------------------------

extern "C" void kernel_launch(void* const* d_in, const int* in_sizes, int n_in,
                              void* d_out, int out_size) {
    const float* emb       = (const float*)d_in[0];
    const float* ctx_Wih_f = (const float*)d_in[1];
    const float* ctx_Whh_f = (const float*)d_in[2];
    const float* ctx_b_f   = (const float*)d_in[3];
    const float* ctx_Wih_b = (const float*)d_in[4];
    const float* ctx_Whh_b = (const float*)d_in[5];
    const float* ctx_b_b   = (const float*)d_in[6];
    const float* agg_Wih_f = (const float*)d_in[7];
    const float* agg_Whh_f = (const float*)d_in[8];
    const float* agg_b_f   = (const float*)d_in[9];
    const float* agg_Wih_b = (const float*)d_in[10];
    const float* agg_Whh_b = (const float*)d_in[11];
    const float* agg_b_b   = (const float*)d_in[12];
    const float* W_full_f  = (const float*)d_in[13];
    const float* W_full_b  = (const float*)d_in[14];
    const float* W_mp_f    = (const float*)d_in[15];
    const float* W_mp_b    = (const float*)d_in[16];
    const float* W_attn_f  = (const float*)d_in[17];
    const float* W_mattn_f = (const float*)d_in[18];
    const float* pred_W1   = (const float*)d_in[19];
    const float* pred_b1   = (const float*)d_in[20];
    const float* pred_W2   = (const float*)d_in[21];
    const float* pred_b2   = (const float*)d_in[22];
    const int*   sa        = (const int*)d_in[23];
    const int*   sb        = (const int*)d_in[24];
    float* out = (float*)d_out;

    static bool attr_set = false;
    const int LSTM_SMEM = (14400 + 9600 + 384 * 16) * 4;   // 120576 B
    if (!attr_set) {
        cudaFuncSetAttribute(lstm_scan_kernel, cudaFuncAttributeMaxDynamicSharedMemorySize, LSTM_SMEM);
        attr_set = true;
    }

    float *s1, *s2, *xg, *o, *on, *hT, *pair, *cosm, *rsum, *csum, *meanb, *maxb, *vbuf, *x1;
    cudaGetSymbolAddress((void**)&s1,   g_s1);
    cudaGetSymbolAddress((void**)&s2,   g_s2);
    cudaGetSymbolAddress((void**)&xg,   g_xg);
    cudaGetSymbolAddress((void**)&o,    g_o);
    cudaGetSymbolAddress((void**)&on,   g_on);
    cudaGetSymbolAddress((void**)&hT,   g_hT);
    cudaGetSymbolAddress((void**)&pair, g_pair);
    cudaGetSymbolAddress((void**)&cosm, g_cos);
    cudaGetSymbolAddress((void**)&rsum, g_rsum);
    cudaGetSymbolAddress((void**)&csum, g_csum);
    cudaGetSymbolAddress((void**)&meanb,g_mean);
    cudaGetSymbolAddress((void**)&maxb, g_maxv);
    cudaGetSymbolAddress((void**)&vbuf, g_v);
    cudaGetSymbolAddress((void**)&x1,   g_x1);

    const size_t SLC = (size_t)BS_ * H_;
    const size_t XSL = (size_t)BS_ * G4_;
    const size_t CSS = (size_t)B_ * S_ * S_;
    const size_t PSS = (size_t)B_ * L_ * S_ * S_;
    const long   SH  = (long)S_ * H_;
    const int    hTN = 2 * 4 * H_ * B_;

    // 1) embedding gather
    gather_emb_kernel<<<BS_, 128>>>(emb, sa, sb, s1, s2);

    // 2) context gate precompute (4 GEMMs)
    dim3 gb((G4_ + 63) / 64, BS_ / 64);
    gemm_bias_kernel<<<gb, 256>>>(s1, ctx_Wih_f, ctx_b_f, xg + 0 * XSL, BS_, G4_, D_);
    gemm_bias_kernel<<<gb, 256>>>(s1, ctx_Wih_b, ctx_b_b, xg + 1 * XSL, BS_, G4_, D_);
    gemm_bias_kernel<<<gb, 256>>>(s2, ctx_Wih_f, ctx_b_f, xg + 2 * XSL, BS_, G4_, D_);
    gemm_bias_kernel<<<gb, 256>>>(s2, ctx_Wih_b, ctx_b_b, xg + 3 * XSL, BS_, G4_, D_);

    // 3) context BiLSTM: one persistent scan
    reset_bar_kernel<<<1, 1>>>();
    zero_kernel<<<(hTN + 255) / 256, 256>>>(hT, hTN);
    lstm_scan_kernel<<<LSTM_BLOCKS, 384, LSTM_SMEM>>>(xg, ctx_Whh_f, ctx_Whh_b, hT, o);

    float* s1f = o;            float* s1b = o + SLC;
    float* s2f = o + 2 * SLC;  float* s2b = o + 3 * SLC;
    float* s1fn = on;          float* s1bn = on + SLC;
    float* s2fn = on + 2*SLC;  float* s2bn = on + 3 * SLC;
    float* v1 = vbuf;          float* v2 = vbuf + (size_t)BS_ * VD_;

    // 4) normalized copies
    normalize_kernel<<<(4 * BS_ * 32 + 255) / 256, 256>>>(o, on, 4 * BS_);

    // 5) pairwise (maxpool) matching
    pairwise_kernel<<<dim3(L_, B_), 256>>>(s1fn, s2bn, W_mp_f, pair);
    pairwise_kernel<<<dim3(L_, B_), 256>>>(s1bn, s2bn, W_mp_b, pair + PSS);
    dim3 gfm(S_, B_);
    pair_max_j_kernel<<<gfm, 32>>>(pair,        v1, 20);
    pair_max_j_kernel<<<gfm, 32>>>(pair + PSS,  v1, 100);
    pair_max_i_kernel<<<gfm, 32>>>(pair,        v2, 20);
    pair_max_i_kernel<<<gfm, 32>>>(pair + PSS,  v2, 100);

    // 6) cosine matrices + sums
    cosine_kernel<<<B_, 256>>>(s1fn, s2fn, cosm);
    cosine_kernel<<<B_, 256>>>(s1bn, s2bn, cosm + CSS);
    cos_sums_kernel<<<B_, S_>>>(cosm,       rsum,           csum);
    cos_sums_kernel<<<B_, S_>>>(cosm + CSS, rsum + B_ * S_, csum + B_ * S_);

    // 7) fused attentive mean/max (f+b in one pass)
    attn_row_kernel<<<dim3(8, B_), 320>>>(cosm, cosm + CSS, s2f, csum, csum + B_ * S_,
                                          meanb + 0 * SLC, meanb + 1 * SLC,
                                          maxb + 0 * SLC,  maxb + 1 * SLC);
    attn_col_kernel<<<dim3(8, B_), 320>>>(cosm, cosm + CSS, s1f, rsum, rsum + B_ * S_,
                                          meanb + 2 * SLC, meanb + 3 * SLC,
                                          maxb + 2 * SLC,  maxb + 3 * SLC);

    // 8) all 16 full matches in one batched launch
    FMArgs16 fa;
    float* z = (float*)0;
    fa.e[0]  = { s1f, s2f + (size_t)(S_ - 1) * H_, SH, 0,  W_full_f,  v1, 0,   0 };
    fa.e[1]  = { s1b, s2b,                         SH, 0,  W_full_b,  v1, 80,  0 };
    fa.e[2]  = { s2f, s1f + (size_t)(S_ - 1) * H_, SH, 0,  W_full_f,  v2, 0,   0 };
    fa.e[3]  = { s2b, s1b,                         SH, 0,  W_full_b,  v2, 80,  0 };
    fa.e[4]  = { s1f, meanb + 0 * SLC, SH, H_, W_attn_f,  v1, 40,  0 };
    fa.e[5]  = { s1b, meanb + 1 * SLC, SH, H_, W_attn_f,  v1, 120, 0 };
    fa.e[6]  = { s2f, meanb + 2 * SLC, SH, H_, W_attn_f,  v2, 40,  0 };
    fa.e[7]  = { s2b, meanb + 3 * SLC, SH, H_, W_attn_f,  v2, 120, 0 };
    fa.e[8]  = { s1f, maxb + 0 * SLC,  SH, H_, W_mattn_f, v1, 60,  0 };
    fa.e[9]  = { s1b, maxb + 1 * SLC,  SH, H_, W_mattn_f, v1, 140, 0 };
    fa.e[10] = { s2f, maxb + 2 * SLC,  SH, H_, W_mattn_f, v2, 60,  0 };
    fa.e[11] = { s2b, maxb + 3 * SLC,  SH, H_, W_mattn_f, v2, 140, 0 };
    fa.e[12] = fa.e[0]; fa.e[13] = fa.e[1]; fa.e[14] = fa.e[2]; fa.e[15] = fa.e[3];
    full_match_batched<<<dim3(S_, B_, 12), 64>>>(fa);
    (void)z;

    // 9) aggregation gate precompute (4 GEMMs, reuse xg)
    gemm_bias_kernel<<<gb, 256>>>(v1, agg_Wih_f, agg_b_f, xg + 0 * XSL, BS_, G4_, VD_);
    gemm_bias_kernel<<<gb, 256>>>(v1, agg_Wih_b, agg_b_b, xg + 1 * XSL, BS_, G4_, VD_);
    gemm_bias_kernel<<<gb, 256>>>(v2, agg_Wih_f, agg_b_f, xg + 2 * XSL, BS_, G4_, VD_);
    gemm_bias_kernel<<<gb, 256>>>(v2, agg_Wih_b, agg_b_b, xg + 3 * XSL, BS_, G4_, VD_);

    // 10) aggregation BiLSTM scan (only final h needed)
    reset_bar_kernel<<<1, 1>>>();
    zero_kernel<<<(hTN + 255) / 256, 256>>>(hT, hTN);
    lstm_scan_kernel<<<LSTM_BLOCKS, 384, LSTM_SMEM>>>(xg, agg_Whh_f, agg_Whh_b, hT, (float*)0);

    // 11) prediction head + log_softmax
    pred1_kernel<<<B_, 640>>>(hT, pred_W1, pred_b1, x1);
    pred2_kernel<<<1, 32>>>(x1, pred_W2, pred_b2, out);
}

// round 3
// speedup vs baseline: 1.9629x; 1.1379x over previous
#include <cuda_runtime.h>
#include <math.h>

#define B_   32
#define S_   64
#define H_   300
#define D_   300
#define L_   20
#define BS_  2048          // B*S
#define G4_  1200          // 4*H
#define VD_  160           // 8*L
#define EPSV 1e-8f
#define LSTM_BLOCKS 100
#define STREAM_BLOCKS 25

typedef unsigned long long u64;
union F4U { float4 f4; u64 u[2]; };

__device__ __forceinline__ u64 pk2(float x) {
    u64 r; asm("mov.b64 %0, {%1, %1};" : "=l"(r) : "f"(x)); return r;
}
__device__ __forceinline__ u64 fma2(u64 a, u64 b, u64 c) {
    u64 d; asm("fma.rn.f32x2 %0, %1, %2, %3;" : "=l"(d) : "l"(a), "l"(b), "l"(c)); return d;
}
__device__ __forceinline__ float2 up2(u64 v) {
    float a, b; asm("mov.b64 {%0, %1}, %2;" : "=f"(a), "=f"(b) : "l"(v));
    return make_float2(a, b);
}

// ------------------------- scratch (static device globals) -------------------
__device__ float g_s1[BS_*D_];
__device__ float g_s2[BS_*D_];
__device__ float g_xg[4*BS_*G4_];
__device__ float g_o[4*BS_*H_];
__device__ float g_on[4*BS_*H_];
__device__ float g_hT[2*4*H_*B_];        // [slot][st][m][b]
__device__ float g_pair[2*B_*L_*S_*S_];
__device__ float g_cos[2*B_*S_*S_];
__device__ float g_rsum[2*B_*S_];
__device__ float g_csum[2*B_*S_];
__device__ float g_mean[4*BS_*H_];
__device__ float g_maxv[4*BS_*H_];
__device__ float g_v[2*BS_*VD_];
__device__ float g_x1[B_*600];
__device__ unsigned g_bar4[4];

// ------------------------------- kernels -------------------------------------

__global__ void zero_kernel(float* p, int n) {
    int i = blockIdx.x * blockDim.x + threadIdx.x;
    if (i < n) p[i] = 0.f;
    if (blockIdx.x == 0 && threadIdx.x < 4) g_bar4[threadIdx.x] = 0u;
}

__global__ void gather_emb_kernel(const float* __restrict__ emb,
                                  const int* __restrict__ ia, const int* __restrict__ ib,
                                  float* __restrict__ s1, float* __restrict__ s2) {
    int row = blockIdx.x;
    int a = ia[row], b = ib[row];
    for (int k = threadIdx.x; k < D_; k += blockDim.x) {
        s1[(size_t)row * D_ + k] = emb[(size_t)a * D_ + k];
        s2[(size_t)row * D_ + k] = emb[(size_t)b * D_ + k];
    }
}

// z=0:(A0,Wf,bf) z=1:(A0,Wb,bb) z=2:(A1,Wf,bf) z=3:(A1,Wb,bb); out = C + z*XSL
__global__ void gemm4_kernel(const float* __restrict__ A0, const float* __restrict__ A1,
                             const float* __restrict__ Wf, const float* __restrict__ Wb,
                             const float* __restrict__ bf, const float* __restrict__ bb,
                             float* __restrict__ C, int M, int N, int K, size_t XSL) {
    int z = blockIdx.z;
    const float* A = (z < 2) ? A0 : A1;
    const float* W = (z & 1) ? Wb : Wf;
    const float* bias = (z & 1) ? bb : bf;
    float* Cz = C + (size_t)z * XSL;

    __shared__ float As[8][68];
    __shared__ float Bs[8][68];
    int tid = threadIdx.x;
    int ti = tid >> 4, tj = tid & 15;
    int m0 = blockIdx.y * 64, n0 = blockIdx.x * 64;
    u64 acc2[4][2] = {};
    for (int k0 = 0; k0 < K; k0 += 8) {
        #pragma unroll
        for (int r = 0; r < 2; r++) {
            int idx = tid + r * 256;
            int row = idx >> 3, col = idx & 7;
            int kk = k0 + col;
            int m = m0 + row;
            int n = n0 + row;
            As[col][row] = (kk < K && m < M) ? A[(size_t)m * K + kk] : 0.f;
            Bs[col][row] = (kk < K && n < N) ? W[(size_t)n * K + kk] : 0.f;
        }
        __syncthreads();
        #pragma unroll
        for (int kk = 0; kk < 8; kk++) {
            float4 a4 = *(const float4*)&As[kk][ti * 4];
            F4U b4; b4.f4 = *(const float4*)&Bs[kk][tj * 4];
            u64 a0 = pk2(a4.x), a1 = pk2(a4.y), a2 = pk2(a4.z), a3 = pk2(a4.w);
            acc2[0][0] = fma2(a0, b4.u[0], acc2[0][0]);
            acc2[0][1] = fma2(a0, b4.u[1], acc2[0][1]);
            acc2[1][0] = fma2(a1, b4.u[0], acc2[1][0]);
            acc2[1][1] = fma2(a1, b4.u[1], acc2[1][1]);
            acc2[2][0] = fma2(a2, b4.u[0], acc2[2][0]);
            acc2[2][1] = fma2(a2, b4.u[1], acc2[2][1]);
            acc2[3][0] = fma2(a3, b4.u[0], acc2[3][0]);
            acc2[3][1] = fma2(a3, b4.u[1], acc2[3][1]);
        }
        __syncthreads();
    }
    #pragma unroll
    for (int r = 0; r < 4; r++) {
        int m = m0 + ti * 4 + r;
        if (m >= M) continue;
        float2 p0 = up2(acc2[r][0]);
        float2 p1 = up2(acc2[r][1]);
        float cv[4] = {p0.x, p0.y, p1.x, p1.y};
        #pragma unroll
        for (int c = 0; c < 4; c++) {
            int n = n0 + tj * 4 + c;
            if (n < N) Cz[(size_t)m * N + n] = cv[c] + bias[n];
        }
    }
}

// ----------------------- persistent BiLSTM scan v2 ---------------------------
__global__ void __launch_bounds__(384, 1)
lstm_scan_kernel(const float* __restrict__ xg,
                 const float* __restrict__ Whf, const float* __restrict__ Whb,
                 float* __restrict__ hT, float* __restrict__ ys) {
    extern __shared__ float sm[];
    float*  w_sm = sm;                       // [48][300]
    float4* h4s  = (float4*)(sm + 14400);    // [300][8] float4
    float*  red  = sm + 14400 + 9600;        // [384][16]

    int tid = threadIdx.x;
    int st = blockIdx.x / STREAM_BLOCKS;
    int chunk = blockIdx.x - st * STREAM_BLOCKS;
    int m0 = chunk * 12;
    const float* W = (st & 1) ? Whb : Whf;
    unsigned* bar = &g_bar4[st];

    for (int idx = tid; idx < 48 * 300; idx += 384) {
        int rr = idx / 300, k = idx - rr * 300;
        int g = rr / 12, r = rr - g * 12;
        w_sm[idx] = W[(size_t)(g * 300 + m0 + r) * 300 + k];
    }

    int kq  = tid / 96;
    int rem = tid - kq * 96;
    int rq  = rem >> 3;
    int bq  = rem & 7;
    int m   = m0 + rq;
    int rev = st & 1;
    float cstate[4] = {0.f, 0.f, 0.f, 0.f};
    const float* wb = w_sm + rq * 300;

    size_t xbase[4];
    #pragma unroll
    for (int bi = 0; bi < 4; bi++)
        xbase[bi] = ((size_t)st * BS_ + (size_t)(bq * 4 + bi) * S_) * G4_;

    for (int s = 0; s < S_; s++) {
        int t = rev ? (S_ - 1 - s) : s;
        // prefetch x gate biases (independent of h) — hides latency behind barrier
        float px[16];
        if (tid < 96) {
            #pragma unroll
            for (int bi = 0; bi < 4; bi++) {
                const float* xr = xg + xbase[bi] + (size_t)t * G4_;
                px[bi * 4 + 0] = xr[m];
                px[bi * 4 + 1] = xr[H_ + m];
                px[bi * 4 + 2] = xr[2 * H_ + m];
                px[bi * 4 + 3] = xr[3 * H_ + m];
            }
        }
        if (s) {
            if (tid == 0) {
                unsigned target = (unsigned)s * STREAM_BLOCKS;
                unsigned v;
                while (1) {
                    asm volatile("ld.acquire.gpu.global.u32 %0, [%1];" : "=r"(v) : "l"(bar));
                    if (v >= target) break;
                    __nanosleep(32);
                }
            }
            __syncthreads();
        }
        // stage h via L2 (bypass possibly-stale L1)
        const float4* hin = (const float4*)(hT + (size_t)((s & 1) * 4 + st) * (H_ * B_));
        for (int idx = tid; idx < 2400; idx += 384) h4s[idx] = __ldcg(hin + idx);
        __syncthreads();

        u64 acc2[8] = {};
        for (int j = kq; j < 75; j += 4) {
            int k = j * 4;
            F4U h0, h1, h2, h3;
            h0.f4 = h4s[k * 8 + bq];
            h1.f4 = h4s[k * 8 + 8 + bq];
            h2.f4 = h4s[k * 8 + 16 + bq];
            h3.f4 = h4s[k * 8 + 24 + bq];
            #pragma unroll
            for (int g = 0; g < 4; g++) {
                float4 w4 = *(const float4*)(wb + g * 3600 + k);
                u64 wx = pk2(w4.x), wy = pk2(w4.y), wz = pk2(w4.z), ww = pk2(w4.w);
                u64 A0 = acc2[g * 2], A1 = acc2[g * 2 + 1];
                A0 = fma2(wx, h0.u[0], A0); A1 = fma2(wx, h0.u[1], A1);
                A0 = fma2(wy, h1.u[0], A0); A1 = fma2(wy, h1.u[1], A1);
                A0 = fma2(wz, h2.u[0], A0); A1 = fma2(wz, h2.u[1], A1);
                A0 = fma2(ww, h3.u[0], A0); A1 = fma2(ww, h3.u[1], A1);
                acc2[g * 2] = A0; acc2[g * 2 + 1] = A1;
            }
        }
        {
            float* rp = red + tid * 16;
            #pragma unroll
            for (int g = 0; g < 4; g++) {
                float2 p0 = up2(acc2[g * 2]);
                float2 p1 = up2(acc2[g * 2 + 1]);
                rp[g * 4 + 0] = p0.x; rp[g * 4 + 1] = p0.y;
                rp[g * 4 + 2] = p1.x; rp[g * 4 + 3] = p1.y;
            }
        }
        __syncthreads();
        if (tid < 96) {
            const float* r0 = red + tid * 16;
            const float* r1 = r0 + 96 * 16;
            const float* r2 = r1 + 96 * 16;
            const float* r3 = r2 + 96 * 16;
            float hnv[4];
            #pragma unroll
            for (int bi = 0; bi < 4; bi++) {
                float ai = px[bi*4+0] + r0[0*4+bi] + r1[0*4+bi] + r2[0*4+bi] + r3[0*4+bi];
                float af = px[bi*4+1] + r0[1*4+bi] + r1[1*4+bi] + r2[1*4+bi] + r3[1*4+bi];
                float ag = px[bi*4+2] + r0[2*4+bi] + r1[2*4+bi] + r2[2*4+bi] + r3[2*4+bi];
                float ao = px[bi*4+3] + r0[3*4+bi] + r1[3*4+bi] + r2[3*4+bi] + r3[3*4+bi];
                float ii = 1.f / (1.f + expf(-ai));
                float ff = 1.f / (1.f + expf(-af));
                float gg = tanhf(ag);
                float oo = 1.f / (1.f + expf(-ao));
                float cn = ff * cstate[bi] + ii * gg;
                cstate[bi] = cn;
                float hn = oo * tanhf(cn);
                hnv[bi] = hn;
                if (ys) ys[((size_t)(st * B_ + (bq * 4 + bi)) * S_ + t) * H_ + m] = hn;
            }
            float* hw = hT + (size_t)(((s + 1) & 1) * 4 + st) * (H_ * B_) + m * B_ + bq * 4;
            *(float4*)hw = make_float4(hnv[0], hnv[1], hnv[2], hnv[3]);
        }
        __threadfence();
        __syncthreads();
        if (tid == 0) atomicAdd(bar, 1u);
    }
}

__global__ void normalize_kernel(const float* __restrict__ in, float* __restrict__ out, int nrows) {
    int warp = (blockIdx.x * blockDim.x + threadIdx.x) >> 5;
    int lane = threadIdx.x & 31;
    if (warp >= nrows) return;
    const float* r = in + (size_t)warp * H_;
    float ss = 0.f;
    for (int k = lane; k < H_; k += 32) { float v = r[k]; ss += v * v; }
    #pragma unroll
    for (int o = 16; o; o >>= 1) ss += __shfl_xor_sync(0xffffffffu, ss, o);
    float inv = rsqrtf(ss);
    float* w = out + (size_t)warp * H_;
    for (int k = lane; k < H_; k += 32) w[k] = r[k] * inv;
}

// ----------------------- batched full match ----------------------------------
struct FMArg { const float* a; const float* c; long bs; long ss; const float* W; float* vout; int off; int pad; };
struct FMArgs16 { FMArg e[12]; };

__global__ void full_match_batched(FMArgs16 args) {
    FMArg A = args.e[blockIdx.z];
    int b = blockIdx.y, sIdx = blockIdx.x;
    __shared__ float a_sm[H_], c_sm[H_];
    const float* a = A.a + ((size_t)b * S_ + sIdx) * H_;
    const float* c = A.c + (size_t)b * A.bs + (size_t)sIdx * A.ss;
    for (int k = threadIdx.x; k < H_; k += blockDim.x) { a_sm[k] = a[k]; c_sm[k] = c[k]; }
    __syncthreads();
    int l = threadIdx.x;
    if (l < L_) {
        const float* w = A.W + l * H_;
        float num = 0.f, na = 0.f, nc = 0.f;
        for (int k = 0; k < H_; k++) {
            float wv = w[k]; float w2 = wv * wv;
            float av = a_sm[k], cv = c_sm[k];
            num += w2 * av * cv; na += w2 * av * av; nc += w2 * cv * cv;
        }
        float d = fmaxf(sqrtf(na), EPSV) * fmaxf(sqrtf(nc), EPSV);
        A.vout[((size_t)b * S_ + sIdx) * VD_ + A.off + l] = num / d;
    }
}

// m_pair[b,l,i,j] = sum_h W2[l,h] s1n[b,i,h] s2n[b,j,h]
__global__ void pairwise_kernel(const float* __restrict__ s1n, const float* __restrict__ s2n,
                                const float* __restrict__ Wm, float* __restrict__ outp) {
    int l = blockIdx.x, b = blockIdx.y;
    __shared__ float s1w[60][64], s2c[60][64];
    const float* w = Wm + l * H_;
    int tid = threadIdx.x;
    int ti = tid >> 4, tj = tid & 15;
    u64 acc2[4][2] = {};
    for (int h0 = 0; h0 < H_; h0 += 60) {
        for (int idx = tid; idx < 64 * 60; idx += 256) {
            int i = idx / 60, hh = idx % 60;
            float wv = w[h0 + hh];
            size_t gi = ((size_t)b * S_ + i) * H_ + h0 + hh;
            s1w[hh][i] = s1n[gi] * wv * wv;
            s2c[hh][i] = s2n[gi];
        }
        __syncthreads();
        #pragma unroll 4
        for (int hh = 0; hh < 60; hh++) {
            float4 a4 = *(const float4*)&s1w[hh][ti * 4];
            F4U b4; b4.f4 = *(const float4*)&s2c[hh][tj * 4];
            u64 a0 = pk2(a4.x), a1 = pk2(a4.y), a2 = pk2(a4.z), a3 = pk2(a4.w);
            acc2[0][0] = fma2(a0, b4.u[0], acc2[0][0]);
            acc2[0][1] = fma2(a0, b4.u[1], acc2[0][1]);
            acc2[1][0] = fma2(a1, b4.u[0], acc2[1][0]);
            acc2[1][1] = fma2(a1, b4.u[1], acc2[1][1]);
            acc2[2][0] = fma2(a2, b4.u[0], acc2[2][0]);
            acc2[2][1] = fma2(a2, b4.u[1], acc2[2][1]);
            acc2[3][0] = fma2(a3, b4.u[0], acc2[3][0]);
            acc2[3][1] = fma2(a3, b4.u[1], acc2[3][1]);
        }
        __syncthreads();
    }
    float* o = outp + ((size_t)b * L_ + l) * S_ * S_;
    #pragma unroll
    for (int r = 0; r < 4; r++) {
        float2 p0 = up2(acc2[r][0]);
        float2 p1 = up2(acc2[r][1]);
        float cv[4] = {p0.x, p0.y, p1.x, p1.y};
        #pragma unroll
        for (int c = 0; c < 4; c++)
            o[(ti * 4 + r) * S_ + tj * 4 + c] = cv[c];
    }
}

__global__ void cosine_kernel(const float* __restrict__ an, const float* __restrict__ bn,
                              float* __restrict__ outp) {
    int b = blockIdx.x;
    __shared__ float s1c[60][64], s2c[60][64];
    int tid = threadIdx.x;
    int ti = tid >> 4, tj = tid & 15;
    u64 acc2[4][2] = {};
    for (int h0 = 0; h0 < H_; h0 += 60) {
        for (int idx = tid; idx < 64 * 60; idx += 256) {
            int i = idx / 60, hh = idx % 60;
            size_t gi = ((size_t)b * S_ + i) * H_ + h0 + hh;
            s1c[hh][i] = an[gi];
            s2c[hh][i] = bn[gi];
        }
        __syncthreads();
        #pragma unroll 4
        for (int hh = 0; hh < 60; hh++) {
            float4 a4 = *(const float4*)&s1c[hh][ti * 4];
            F4U b4; b4.f4 = *(const float4*)&s2c[hh][tj * 4];
            u64 a0 = pk2(a4.x), a1 = pk2(a4.y), a2 = pk2(a4.z), a3 = pk2(a4.w);
            acc2[0][0] = fma2(a0, b4.u[0], acc2[0][0]);
            acc2[0][1] = fma2(a0, b4.u[1], acc2[0][1]);
            acc2[1][0] = fma2(a1, b4.u[0], acc2[1][0]);
            acc2[1][1] = fma2(a1, b4.u[1], acc2[1][1]);
            acc2[2][0] = fma2(a2, b4.u[0], acc2[2][0]);
            acc2[2][1] = fma2(a2, b4.u[1], acc2[2][1]);
            acc2[3][0] = fma2(a3, b4.u[0], acc2[3][0]);
            acc2[3][1] = fma2(a3, b4.u[1], acc2[3][1]);
        }
        __syncthreads();
    }
    float* o = outp + (size_t)b * S_ * S_;
    #pragma unroll
    for (int r = 0; r < 4; r++) {
        float2 p0 = up2(acc2[r][0]);
        float2 p1 = up2(acc2[r][1]);
        float cv[4] = {p0.x, p0.y, p1.x, p1.y};
        #pragma unroll
        for (int c = 0; c < 4; c++)
            o[(ti * 4 + r) * S_ + tj * 4 + c] = cv[c];
    }
}

__global__ void cos_sums_kernel(const float* __restrict__ cosm,
                                float* __restrict__ rsum, float* __restrict__ csum) {
    int b = blockIdx.x, t = threadIdx.x;
    const float* cb = cosm + (size_t)b * S_ * S_;
    float sj = 0.f, si = 0.f;
    for (int k = 0; k < S_; k++) { sj += cb[t * S_ + k]; si += cb[k * S_ + t]; }
    csum[b * S_ + t] = sj;
    rsum[b * S_ + t] = si;
}

__global__ void attn_row_kernel(const float* __restrict__ cosf, const float* __restrict__ cosb,
                                const float* __restrict__ src,
                                const float* __restrict__ sumf, const float* __restrict__ sumb,
                                float* __restrict__ mf_o, float* __restrict__ mb_o,
                                float* __restrict__ xf_o, float* __restrict__ xb_o) {
    __shared__ float cf_sm[8 * 64], cb_sm[8 * 64];
    int b = blockIdx.y, i0 = blockIdx.x * 8;
    int tid = threadIdx.x;
    for (int idx = tid; idx < 512; idx += 320) {
        int q = idx >> 6, j = idx & 63;
        cf_sm[idx] = cosf[(size_t)b * 4096 + (i0 + q) * 64 + j];
        cb_sm[idx] = cosb[(size_t)b * 4096 + (i0 + q) * 64 + j];
    }
    __syncthreads();
    int h = tid;
    if (h >= H_) return;
    float accf[8] = {}, accb[8] = {}, mxf[8], mxb[8];
    #pragma unroll
    for (int q = 0; q < 8; q++) { mxf[q] = -INFINITY; mxb[q] = -INFINITY; }
    for (int j4 = 0; j4 < 64; j4 += 4) {
        float v0 = src[((size_t)b * 64 + j4 + 0) * H_ + h];
        float v1 = src[((size_t)b * 64 + j4 + 1) * H_ + h];
        float v2 = src[((size_t)b * 64 + j4 + 2) * H_ + h];
        float v3 = src[((size_t)b * 64 + j4 + 3) * H_ + h];
        #pragma unroll
        for (int q = 0; q < 8; q++) {
            float4 c4 = *(const float4*)&cf_sm[q * 64 + j4];
            float4 d4 = *(const float4*)&cb_sm[q * 64 + j4];
            float p;
            p = c4.x * v0; accf[q] += p; mxf[q] = fmaxf(mxf[q], p);
            p = c4.y * v1; accf[q] += p; mxf[q] = fmaxf(mxf[q], p);
            p = c4.z * v2; accf[q] += p; mxf[q] = fmaxf(mxf[q], p);
            p = c4.w * v3; accf[q] += p; mxf[q] = fmaxf(mxf[q], p);
            p = d4.x * v0; accb[q] += p; mxb[q] = fmaxf(mxb[q], p);
            p = d4.y * v1; accb[q] += p; mxb[q] = fmaxf(mxb[q], p);
            p = d4.z * v2; accb[q] += p; mxb[q] = fmaxf(mxb[q], p);
            p = d4.w * v3; accb[q] += p; mxb[q] = fmaxf(mxb[q], p);
        }
    }
    #pragma unroll
    for (int q = 0; q < 8; q++) {
        int i = i0 + q;
        size_t o = ((size_t)b * 64 + i) * H_ + h;
        mf_o[o] = accf[q] / sumf[b * 64 + i];
        mb_o[o] = accb[q] / sumb[b * 64 + i];
        xf_o[o] = mxf[q]; xb_o[o] = mxb[q];
    }
}

__global__ void attn_col_kernel(const float* __restrict__ cosf, const float* __restrict__ cosb,
                                const float* __restrict__ src,
                                const float* __restrict__ sumf, const float* __restrict__ sumb,
                                float* __restrict__ mf_o, float* __restrict__ mb_o,
                                float* __restrict__ xf_o, float* __restrict__ xb_o) {
    __shared__ float cf_sm[8 * 64], cb_sm[8 * 64];
    int b = blockIdx.y, j0 = blockIdx.x * 8;
    int tid = threadIdx.x;
    for (int idx = tid; idx < 512; idx += 320) {
        int q = idx >> 6, i = idx & 63;
        cf_sm[idx] = cosf[(size_t)b * 4096 + i * 64 + j0 + q];
        cb_sm[idx] = cosb[(size_t)b * 4096 + i * 64 + j0 + q];
    }
    __syncthreads();
    int h = tid;
    if (h >= H_) return;
    float accf[8] = {}, accb[8] = {}, mxf[8], mxb[8];
    #pragma unroll
    for (int q = 0; q < 8; q++) { mxf[q] = -INFINITY; mxb[q] = -INFINITY; }
    for (int i4 = 0; i4 < 64; i4 += 4) {
        float v0 = src[((size_t)b * 64 + i4 + 0) * H_ + h];
        float v1 = src[((size_t)b * 64 + i4 + 1) * H_ + h];
        float v2 = src[((size_t)b * 64 + i4 + 2) * H_ + h];
        float v3 = src[((size_t)b * 64 + i4 + 3) * H_ + h];
        #pragma unroll
        for (int q = 0; q < 8; q++) {
            float4 c4 = *(const float4*)&cf_sm[q * 64 + i4];
            float4 d4 = *(const float4*)&cb_sm[q * 64 + i4];
            float p;
            p = c4.x * v0; accf[q] += p; mxf[q] = fmaxf(mxf[q], p);
            p = c4.y * v1; accf[q] += p; mxf[q] = fmaxf(mxf[q], p);
            p = c4.z * v2; accf[q] += p; mxf[q] = fmaxf(mxf[q], p);
            p = c4.w * v3; accf[q] += p; mxf[q] = fmaxf(mxf[q], p);
            p = d4.x * v0; accb[q] += p; mxb[q] = fmaxf(mxb[q], p);
            p = d4.y * v1; accb[q] += p; mxb[q] = fmaxf(mxb[q], p);
            p = d4.z * v2; accb[q] += p; mxb[q] = fmaxf(mxb[q], p);
            p = d4.w * v3; accb[q] += p; mxb[q] = fmaxf(mxb[q], p);
        }
    }
    #pragma unroll
    for (int q = 0; q < 8; q++) {
        int j = j0 + q;
        size_t o = ((size_t)b * 64 + j) * H_ + h;
        mf_o[o] = accf[q] / sumf[b * 64 + j];
        mb_o[o] = accb[q] / sumb[b * 64 + j];
        xf_o[o] = mxf[q]; xb_o[o] = mxb[q];
    }
}

__global__ void pair_max_j_kernel(const float* __restrict__ pair, float* __restrict__ vout, int off) {
    int b = blockIdx.y, i = blockIdx.x, l = threadIdx.x;
    if (l >= L_) return;
    const float* p = pair + (((size_t)b * L_ + l) * S_ + i) * S_;
    float m = -INFINITY;
    for (int j = 0; j < S_; j++) m = fmaxf(m, p[j]);
    vout[((size_t)b * S_ + i) * VD_ + off + l] = m;
}

__global__ void pair_max_i_kernel(const float* __restrict__ pair, float* __restrict__ vout, int off) {
    int b = blockIdx.y, j = blockIdx.x, l = threadIdx.x;
    if (l >= L_) return;
    const float* p = pair + ((size_t)b * L_ + l) * S_ * S_ + j;
    float m = -INFINITY;
    for (int i = 0; i < S_; i++) m = fmaxf(m, p[i * S_]);
    vout[((size_t)b * S_ + j) * VD_ + off + l] = m;
}

__global__ void pred1_kernel(const float* __restrict__ hT, const float* __restrict__ W1,
                             const float* __restrict__ b1, float* __restrict__ x) {
    int b = blockIdx.x;
    __shared__ float mv[G4_];
    for (int k = threadIdx.x; k < G4_; k += blockDim.x) {
        int st = k / H_, m = k % H_;
        mv[k] = hT[(size_t)st * (H_ * B_) + m * B_ + b];
    }
    __syncthreads();
    int j = threadIdx.x;
    if (j < 600) {
        const float* w = W1 + (size_t)j * G4_;
        float acc = b1[j];
        for (int k = 0; k < G4_; k++) acc += mv[k] * w[k];
        x[b * 600 + j] = tanhf(acc);
    }
}

__global__ void pred2_kernel(const float* __restrict__ x, const float* __restrict__ W2,
                             const float* __restrict__ b2, float* __restrict__ out) {
    int b = threadIdx.x;
    if (b >= B_) return;
    float z0 = b2[0], z1 = b2[1];
    for (int k = 0; k < 600; k++) {
        float v = x[b * 600 + k];
        z0 += v * W2[k];
        z1 += v * W2[600 + k];
    }
    float m = fmaxf(z0, z1);
    float lse = m + logf(expf(z0 - m) + expf(z1 - m));
    out[b * 2 + 0] = z0 - lse;
    out[b * 2 + 1] = z1 - lse;
}

// ------------------------------- host ----------------------------------------

extern "C" void kernel_launch(void* const* d_in, const int* in_sizes, int n_in,
                              void* d_out, int out_size) {
    const float* emb       = (const float*)d_in[0];
    const float* ctx_Wih_f = (const float*)d_in[1];
    const float* ctx_Whh_f = (const float*)d_in[2];
    const float* ctx_b_f   = (const float*)d_in[3];
    const float* ctx_Wih_b = (const float*)d_in[4];
    const float* ctx_Whh_b = (const float*)d_in[5];
    const float* ctx_b_b   = (const float*)d_in[6];
    const float* agg_Wih_f = (const float*)d_in[7];
    const float* agg_Whh_f = (const float*)d_in[8];
    const float* agg_b_f   = (const float*)d_in[9];
    const float* agg_Wih_b = (const float*)d_in[10];
    const float* agg_Whh_b = (const float*)d_in[11];
    const float* agg_b_b   = (const float*)d_in[12];
    const float* W_full_f  = (const float*)d_in[13];
    const float* W_full_b  = (const float*)d_in[14];
    const float* W_mp_f    = (const float*)d_in[15];
    const float* W_mp_b    = (const float*)d_in[16];
    const float* W_attn_f  = (const float*)d_in[17];
    const float* W_mattn_f = (const float*)d_in[18];
    const float* pred_W1   = (const float*)d_in[19];
    const float* pred_b1   = (const float*)d_in[20];
    const float* pred_W2   = (const float*)d_in[21];
    const float* pred_b2   = (const float*)d_in[22];
    const int*   sa        = (const int*)d_in[23];
    const int*   sb        = (const int*)d_in[24];
    float* out = (float*)d_out;

    static bool attr_set = false;
    const int LSTM_SMEM = (14400 + 9600 + 384 * 16) * 4;
    if (!attr_set) {
        cudaFuncSetAttribute(lstm_scan_kernel, cudaFuncAttributeMaxDynamicSharedMemorySize, LSTM_SMEM);
        attr_set = true;
    }

    float *s1, *s2, *xg, *o, *on, *hT, *pair, *cosm, *rsum, *csum, *meanb, *maxb, *vbuf, *x1;
    cudaGetSymbolAddress((void**)&s1,   g_s1);
    cudaGetSymbolAddress((void**)&s2,   g_s2);
    cudaGetSymbolAddress((void**)&xg,   g_xg);
    cudaGetSymbolAddress((void**)&o,    g_o);
    cudaGetSymbolAddress((void**)&on,   g_on);
    cudaGetSymbolAddress((void**)&hT,   g_hT);
    cudaGetSymbolAddress((void**)&pair, g_pair);
    cudaGetSymbolAddress((void**)&cosm, g_cos);
    cudaGetSymbolAddress((void**)&rsum, g_rsum);
    cudaGetSymbolAddress((void**)&csum, g_csum);
    cudaGetSymbolAddress((void**)&meanb,g_mean);
    cudaGetSymbolAddress((void**)&maxb, g_maxv);
    cudaGetSymbolAddress((void**)&vbuf, g_v);
    cudaGetSymbolAddress((void**)&x1,   g_x1);

    const size_t SLC = (size_t)BS_ * H_;
    const size_t XSL = (size_t)BS_ * G4_;
    const size_t CSS = (size_t)B_ * S_ * S_;
    const size_t PSS = (size_t)B_ * L_ * S_ * S_;
    const long   SH  = (long)S_ * H_;
    const int    hTN = 2 * 4 * H_ * B_;

    gather_emb_kernel<<<BS_, 128>>>(emb, sa, sb, s1, s2);

    // ctx gate precompute: one batched launch (z = 4 GEMMs)
    dim3 gb((G4_ + 63) / 64, BS_ / 64, 4);
    gemm4_kernel<<<gb, 256>>>(s1, s2, ctx_Wih_f, ctx_Wih_b, ctx_b_f, ctx_b_b,
                              xg, BS_, G4_, D_, XSL);

    zero_kernel<<<(hTN + 255) / 256, 256>>>(hT, hTN);
    lstm_scan_kernel<<<LSTM_BLOCKS, 384, LSTM_SMEM>>>(xg, ctx_Whh_f, ctx_Whh_b, hT, o);

    float* s1f = o;            float* s1b = o + SLC;
    float* s2f = o + 2 * SLC;  float* s2b = o + 3 * SLC;
    float* s1fn = on;          float* s1bn = on + SLC;
    float* s2fn = on + 2*SLC;  float* s2bn = on + 3 * SLC;
    float* v1 = vbuf;          float* v2 = vbuf + (size_t)BS_ * VD_;

    normalize_kernel<<<(4 * BS_ * 32 + 255) / 256, 256>>>(o, on, 4 * BS_);

    pairwise_kernel<<<dim3(L_, B_), 256>>>(s1fn, s2bn, W_mp_f, pair);
    pairwise_kernel<<<dim3(L_, B_), 256>>>(s1bn, s2bn, W_mp_b, pair + PSS);
    dim3 gfm(S_, B_);
    pair_max_j_kernel<<<gfm, 32>>>(pair,        v1, 20);
    pair_max_j_kernel<<<gfm, 32>>>(pair + PSS,  v1, 100);
    pair_max_i_kernel<<<gfm, 32>>>(pair,        v2, 20);
    pair_max_i_kernel<<<gfm, 32>>>(pair + PSS,  v2, 100);

    cosine_kernel<<<B_, 256>>>(s1fn, s2fn, cosm);
    cosine_kernel<<<B_, 256>>>(s1bn, s2bn, cosm + CSS);
    cos_sums_kernel<<<B_, S_>>>(cosm,       rsum,           csum);
    cos_sums_kernel<<<B_, S_>>>(cosm + CSS, rsum + B_ * S_, csum + B_ * S_);

    attn_row_kernel<<<dim3(8, B_), 320>>>(cosm, cosm + CSS, s2f, csum, csum + B_ * S_,
                                          meanb + 0 * SLC, meanb + 1 * SLC,
                                          maxb + 0 * SLC,  maxb + 1 * SLC);
    attn_col_kernel<<<dim3(8, B_), 320>>>(cosm, cosm + CSS, s1f, rsum, rsum + B_ * S_,
                                          meanb + 2 * SLC, meanb + 3 * SLC,
                                          maxb + 2 * SLC,  maxb + 3 * SLC);

    FMArgs16 fa;
    fa.e[0]  = { s1f, s2f + (size_t)(S_ - 1) * H_, SH, 0,  W_full_f,  v1, 0,   0 };
    fa.e[1]  = { s1b, s2b,                         SH, 0,  W_full_b,  v1, 80,  0 };
    fa.e[2]  = { s2f, s1f + (size_t)(S_ - 1) * H_, SH, 0,  W_full_f,  v2, 0,   0 };
    fa.e[3]  = { s2b, s1b,                         SH, 0,  W_full_b,  v2, 80,  0 };
    fa.e[4]  = { s1f, meanb + 0 * SLC, SH, H_, W_attn_f,  v1, 40,  0 };
    fa.e[5]  = { s1b, meanb + 1 * SLC, SH, H_, W_attn_f,  v1, 120, 0 };
    fa.e[6]  = { s2f, meanb + 2 * SLC, SH, H_, W_attn_f,  v2, 40,  0 };
    fa.e[7]  = { s2b, meanb + 3 * SLC, SH, H_, W_attn_f,  v2, 120, 0 };
    fa.e[8]  = { s1f, maxb + 0 * SLC,  SH, H_, W_mattn_f, v1, 60,  0 };
    fa.e[9]  = { s1b, maxb + 1 * SLC,  SH, H_, W_mattn_f, v1, 140, 0 };
    fa.e[10] = { s2f, maxb + 2 * SLC,  SH, H_, W_mattn_f, v2, 60,  0 };
    fa.e[11] = { s2b, maxb + 3 * SLC,  SH, H_, W_mattn_f, v2, 140, 0 };
    full_match_batched<<<dim3(S_, B_, 12), 64>>>(fa);

    // agg gate precompute: one batched launch
    gemm4_kernel<<<gb, 256>>>(v1, v2, agg_Wih_f, agg_Wih_b, agg_b_f, agg_b_b,
                              xg, BS_, G4_, VD_, XSL);

    zero_kernel<<<(hTN + 255) / 256, 256>>>(hT, hTN);
    lstm_scan_kernel<<<LSTM_BLOCKS, 384, LSTM_SMEM>>>(xg, agg_Whh_f, agg_Whh_b, hT, (float*)0);

    pred1_kernel<<<B_, 640>>>(hT, pred_W1, pred_b1, x1);
    pred2_kernel<<<1, 32>>>(x1, pred_W2, pred_b2, out);
}